// round 17
// baseline (speedup 1.0000x reference)
#include <cuda_runtime.h>
#include <cuda_fp16.h>

#define NN 100000
#define NE 1000000
#define SLOTS 64              // fixed bucket slots per node (self + in-edges; Poisson(10))
#define SPILLMAX 4096
#define AGG2_GRID 888         // persistent: 148 SMs x 6 blocks

// ---------------- scratch (static device globals; no allocation) ----------------
__device__ __half g_xh[NN * 32];     // x in fp16, rows padded to 32 halves (64B)
__device__ __half g_fh[NN * 64];     // layer1 output in fp16 (128B rows)
__device__ float  g_as[NN], g_ad[NN];    // layer1 logit projections
__device__ float  g_as2[NN], g_ad2[NN];  // layer2 logit projections
__device__ int    g_cnt[NN];         // bucket fill count (starts at 1: self loop)
__device__ int    g_slots[NN * SLOTS];   // src ids; slot 0 = self
__device__ int    g_spill_s[SPILLMAX], g_spill_d[SPILLMAX];
__device__ int    g_spillcnt;
__device__ int    g_is64;
__device__ int    g_done;
__device__ float  g_va2[64], g_vd2[64];  // W2 @ a_src2 / a_dst2
__device__ float  g_csum[64 * 32];       // padded column sums (128B stride)

__device__ __forceinline__ float lrelu(float e) { return (e > 0.f) ? e : 0.2f * e; }

// ---------------- fused init + prep ----------------
__global__ void __launch_bounds__(256)
k_init_prep(const float* __restrict__ x, const int* __restrict__ e,
            const float* __restrict__ W1, const float* __restrict__ as1,
            const float* __restrict__ ad1,
            const float* __restrict__ W2, const float* __restrict__ as2,
            const float* __restrict__ ad2) {
    __shared__ float s_va1[20], s_vd1[20];
    int t = threadIdx.x;
    int n = blockIdx.x * 256 + t;
    if (n < NN) {
        g_cnt[n] = 1;                        // self loop pre-seeded in slot 0
        g_slots[(size_t)n * SLOTS] = n;
    }
    if (n < 64 * 32) g_csum[n] = 0.f;
    if (n == 0) { g_done = 0; g_spillcnt = 0; }
    if (t < 20) {
        float s = 0.f;
        for (int c = 0; c < 64; c++) s += W1[t * 64 + c] * as1[c];
        s_va1[t] = s;
    } else if (t < 40) {
        int k = t - 20; float s = 0.f;
        for (int c = 0; c < 64; c++) s += W1[k * 64 + c] * ad1[c];
        s_vd1[k] = s;
    }
    if (blockIdx.x == 0) {
        if (t == 64) {
            int allz = 1;                    // int64: odd words are zero high halves
            for (int j = 1; j < 64; j += 2)
                if (e[j] != 0) allz = 0;
            g_is64 = allz;
        }
        if (t >= 128 && t < 192) {
            int k = t - 128; float s = 0.f;
            for (int c = 0; c < 64; c++) s += W2[k * 64 + c] * as2[c];
            g_va2[k] = s;
        } else if (t >= 192) {
            int k = t - 192; float s = 0.f;
            for (int c = 0; c < 64; c++) s += W2[k * 64 + c] * ad2[c];
            g_vd2[k] = s;
        }
    }
    __syncthreads();
    if (n >= NN) return;
    const float4* r4 = (const float4*)(x + (size_t)n * 20);
    float v[20];
    #pragma unroll
    for (int q = 0; q < 5; q++) {
        float4 tv = r4[q];
        v[4 * q] = tv.x; v[4 * q + 1] = tv.y; v[4 * q + 2] = tv.z; v[4 * q + 3] = tv.w;
    }
    float ps = 0.f, pd = 0.f;
    __half2* xo = (__half2*)(g_xh + (size_t)n * 32);
    #pragma unroll
    for (int k = 0; k < 20; k += 2) {
        ps += v[k] * s_va1[k] + v[k + 1] * s_va1[k + 1];
        pd += v[k] * s_vd1[k] + v[k + 1] * s_vd1[k + 1];
        xo[k >> 1] = __floats2half2_rn(v[k], v[k + 1]);
    }
    #pragma unroll
    for (int k = 10; k < 16; k++) xo[k] = __floats2half2_rn(0.f, 0.f);  // zero pad
    g_as[n] = ps; g_ad[n] = pd;
}

// ---------------- one-pass bucket scatter ----------------
__global__ void k_scatter(const void* __restrict__ ei) {
    int q = blockIdx.x * blockDim.x + threadIdx.x;   // quad of edges
    if (q >= NE / 4) return;
    int s[4], d[4];
    if (g_is64) {
        const longlong2* ps = (const longlong2*)ei;
        const longlong2* pd = (const longlong2*)((const long long*)ei + NE);
        longlong2 a = ps[2 * q], b = ps[2 * q + 1];
        longlong2 c = pd[2 * q], f = pd[2 * q + 1];
        s[0] = (int)a.x; s[1] = (int)a.y; s[2] = (int)b.x; s[3] = (int)b.y;
        d[0] = (int)c.x; d[1] = (int)c.y; d[2] = (int)f.x; d[3] = (int)f.y;
    } else {
        int4 a = ((const int4*)ei)[q];
        int4 f = ((const int4*)((const int*)ei + NE))[q];
        s[0] = a.x; s[1] = a.y; s[2] = a.z; s[3] = a.w;
        d[0] = f.x; d[1] = f.y; d[2] = f.z; d[3] = f.w;
    }
    #pragma unroll
    for (int i = 0; i < 4; i++) {
        if ((unsigned)d[i] < NN && (unsigned)s[i] < NN) {
            int p = atomicAdd(&g_cnt[d[i]], 1);
            if (p < SLOTS) {
                g_slots[(size_t)d[i] * SLOTS + p] = s[i];
            } else {                           // never hit at this degree dist
                int sp = atomicAdd(&g_spillcnt, 1);
                if (sp < SPILLMAX) { g_spill_s[sp] = s[i]; g_spill_d[sp] = d[i]; }
            }
        }
    }
}

// ---------------- layer 1: softmax-agg x (fp16/HFMA2), fused W1 GEMV, fused proj2 --
// Phase B: 8 groups x 4 lanes; lane loads float4 (8 halves) -> 8 edges/iteration.
__global__ void __launch_bounds__(512)
k_agg1(const float* __restrict__ W1, const float* __restrict__ b1) {
    __shared__ float  s_W1[20 * 64];
    __shared__ float2 s_ew[16][SLOTS];   // phase A: (srcbits, wgt); after prepack:
                                         // (byte-offset bits, half2(wgt*inv) bits)
    for (int i = threadIdx.x; i < 20 * 64; i += 512) s_W1[i] = W1[i];
    __syncthreads();

    int w = (blockIdx.x * 512 + threadIdx.x) >> 5;    // grid exact: NN/16 warps
    int lane = threadIdx.x & 31;
    int wl = threadIdx.x >> 5;
    int deg = g_cnt[w];                  // includes self (slot 0)
    int nm = deg < SLOTS ? deg : SLOTS;
    float adi = g_ad[w];
    const int* slot = g_slots + (size_t)w * SLOTS;
    int sc = g_spillcnt;

    // phase A: lane-parallel weights into smem + denominator
    float denom = 0.f;
    for (int j = lane; j < nm; j += 32) {
        int s = slot[j];
        float wg = __expf(lrelu(g_as[s] + adi));
        s_ew[wl][j] = make_float2(__int_as_float(s), wg);
        denom += wg;
    }
    for (int i = 0; i < sc; i++)
        if (g_spill_d[i] == w && lane == 0)
            denom += __expf(lrelu(g_as[g_spill_s[i]] + adi));
    for (int o = 16; o; o >>= 1) denom += __shfl_xor_sync(0xffffffffu, denom, o);
    float inv = 1.f / denom;
    // prepack: byte offset (s<<6) + packed half2 normalized weight
    for (int j = lane; j < nm; j += 32) {
        float2 e = s_ew[wl][j];
        __half2 wh = __float2half2_rn(e.y * inv);
        s_ew[wl][j] = make_float2(__int_as_float(__float_as_int(e.x) << 6),
                                  __uint_as_float(*(unsigned*)&wh));
    }
    __syncwarp();

    // phase B: grouped gathers, pure LDS+LDG+HFMA2
    int g = lane >> 2, lc = lane & 3;
    const char* xb_l = (const char*)g_xh + lc * 16;
    __half2 acch[4];
    #pragma unroll
    for (int k = 0; k < 4; k++) acch[k] = __floats2half2_rn(0.f, 0.f);
    for (int j = g; j < nm; j += 8) {
        float2 e = s_ew[wl][j];
        unsigned whb = __float_as_uint(e.y);
        __half2 wh = *(__half2*)&whb;
        float4 hv = *(const float4*)(xb_l + __float_as_int(e.x));
        const __half2* hp = (const __half2*)&hv;
        acch[0] = __hfma2(wh, hp[0], acch[0]);
        acch[1] = __hfma2(wh, hp[1], acch[1]);
        acch[2] = __hfma2(wh, hp[2], acch[2]);
        acch[3] = __hfma2(wh, hp[3], acch[3]);
    }
    for (int i = 0; i < sc; i++) {               // rare: spill edges via group 0
        if (g_spill_d[i] == w) {
            int s = g_spill_s[i];
            float wgf = __expf(lrelu(g_as[s] + adi)) * inv;
            if (g == 0) {
                __half2 wh = __float2half2_rn(wgf);
                float4 hv = *(const float4*)(xb_l + (s << 6));
                const __half2* hp = (const __half2*)&hv;
                #pragma unroll
                for (int k = 0; k < 4; k++) acch[k] = __hfma2(wh, hp[k], acch[k]);
            }
        }
    }
    // to fp32, cross-group reduction: lanes w/ same lc hold col sums (col = 8lc+k)
    float acc[8];
    #pragma unroll
    for (int k = 0; k < 4; k++) {
        float2 f = __half22float2(acch[k]);
        acc[2 * k] = f.x; acc[2 * k + 1] = f.y;
    }
    #pragma unroll
    for (int k = 0; k < 8; k++) {
        acc[k] += __shfl_xor_sync(0xffffffffu, acc[k], 4);
        acc[k] += __shfl_xor_sync(0xffffffffu, acc[k], 8);
        acc[k] += __shfl_xor_sync(0xffffffffu, acc[k], 16);
    }

    // fused GEMV: out[c] = sum_kk agg[kk] * W1[kk][c]; agg[kk] on lane kk>>3, reg kk&7
    float o0 = 0.f, o1 = 0.f;
    #pragma unroll
    for (int kk = 0; kk < 20; kk++) {
        float xk = __shfl_sync(0xffffffffu, acc[kk & 7], kk >> 3);
        float2 wv = ((const float2*)(s_W1 + kk * 64))[lane];
        o0 += xk * wv.x;
        o1 += xk * wv.y;
    }
    float2 bv = ((const float2*)b1)[lane];
    o0 = fmaxf(o0 + bv.x, 0.f);
    o1 = fmaxf(o1 + bv.y, 0.f);
    ((__half2*)g_fh)[(size_t)w * 32 + lane] = __floats2half2_rn(o0, o1);

    // fused layer-2 logit projections
    float2 va = ((const float2*)g_va2)[lane];
    float2 vd = ((const float2*)g_vd2)[lane];
    float ps = o0 * va.x + o1 * va.y;
    float pd = o0 * vd.x + o1 * vd.y;
    for (int o = 16; o; o >>= 1) {
        ps += __shfl_xor_sync(0xffffffffu, ps, o);
        pd += __shfl_xor_sync(0xffffffffu, pd, o);
    }
    if (lane == 0) { g_as2[w] = ps; g_ad2[w] = pd; }
}

// ---------------- layer 2: softmax-agg feat (fp16/HFMA2) + fused mean + final ------
// Phase B: 4 groups x 8 lanes; lane loads float4 (8 halves) -> 4 edges/iteration.
__global__ void __launch_bounds__(256)
k_agg2(const float* __restrict__ W2, const float* __restrict__ b2,
       float* __restrict__ out) {
    __shared__ float2 s_ew[8][SLOTS];
    __shared__ float  s_red[8][64];
    __shared__ int    s_last;
    int lane = threadIdx.x & 31;
    int wl = threadIdx.x >> 5;
    int gw = (blockIdx.x * 256 + threadIdx.x) >> 5;
    int nwarps = AGG2_GRID * 8;
    int g = lane >> 3, lc = lane & 7;
    const char* fb_l = (const char*)g_fh + lc * 16;
    int sc = g_spillcnt;

    float ttot[8];                        // persistent col totals (col = 8*lc + k)
    #pragma unroll
    for (int k = 0; k < 8; k++) ttot[k] = 0.f;

    for (int w = gw; w < NN; w += nwarps) {
        int deg = g_cnt[w];               // includes self (slot 0)
        int nm = deg < SLOTS ? deg : SLOTS;
        float adi = g_ad2[w];
        const int* slot = g_slots + (size_t)w * SLOTS;

        float denom = 0.f;
        for (int j = lane; j < nm; j += 32) {
            int s = slot[j];
            float wg = __expf(lrelu(g_as2[s] + adi));
            s_ew[wl][j] = make_float2(__int_as_float(s), wg);
            denom += wg;
        }
        for (int i = 0; i < sc; i++)
            if (g_spill_d[i] == w && lane == 0)
                denom += __expf(lrelu(g_as2[g_spill_s[i]] + adi));
        for (int o = 16; o; o >>= 1) denom += __shfl_xor_sync(0xffffffffu, denom, o);
        float inv = 1.f / denom;
        for (int j = lane; j < nm; j += 32) {     // prepack: offset + half2 weight
            float2 e = s_ew[wl][j];
            __half2 wh = __float2half2_rn(e.y * inv);
            s_ew[wl][j] = make_float2(__int_as_float(__float_as_int(e.x) << 7),
                                      __uint_as_float(*(unsigned*)&wh));
        }
        __syncwarp();

        __half2 acch[4];
        #pragma unroll
        for (int k = 0; k < 4; k++) acch[k] = __floats2half2_rn(0.f, 0.f);
        for (int j = g; j < nm; j += 4) {
            float2 e = s_ew[wl][j];
            unsigned whb = __float_as_uint(e.y);
            __half2 wh = *(__half2*)&whb;
            float4 hv = *(const float4*)(fb_l + __float_as_int(e.x));
            const __half2* hp = (const __half2*)&hv;
            acch[0] = __hfma2(wh, hp[0], acch[0]);
            acch[1] = __hfma2(wh, hp[1], acch[1]);
            acch[2] = __hfma2(wh, hp[2], acch[2]);
            acch[3] = __hfma2(wh, hp[3], acch[3]);
        }
        for (int i = 0; i < sc; i++) {        // rare: spill via group 0
            if (g_spill_d[i] == w) {
                int s = g_spill_s[i];
                float wgf = __expf(lrelu(g_as2[s] + adi)) * inv;
                if (g == 0) {
                    __half2 wh = __float2half2_rn(wgf);
                    float4 hv = *(const float4*)(fb_l + (s << 7));
                    const __half2* hp = (const __half2*)&hv;
                    #pragma unroll
                    for (int k = 0; k < 4; k++) acch[k] = __hfma2(wh, hp[k], acch[k]);
                }
            }
        }
        #pragma unroll
        for (int k = 0; k < 4; k++) {         // node done: fold into fp32 totals
            float2 f = __half22float2(acch[k]);
            ttot[2 * k]     += f.x;
            ttot[2 * k + 1] += f.y;
        }
        __syncwarp();
    }

    // one deferred cross-group reduction per warp
    #pragma unroll
    for (int k = 0; k < 8; k++) {
        ttot[k] += __shfl_xor_sync(0xffffffffu, ttot[k], 8);
        ttot[k] += __shfl_xor_sync(0xffffffffu, ttot[k], 16);
    }
    if (lane < 8) {
        #pragma unroll
        for (int k = 0; k < 8; k++) s_red[wl][8 * lane + k] = ttot[k];
    }
    __syncthreads();
    if (threadIdx.x < 64) {
        float t = 0.f;
        #pragma unroll
        for (int i = 0; i < 8; i++) t += s_red[i][threadIdx.x];
        atomicAdd(&g_csum[threadIdx.x * 32], t);   // 128B stride -> spread LTS
        __threadfence();
    }
    __syncthreads();
    if (threadIdx.x == 0)
        s_last = (atomicAdd(&g_done, 1) == AGG2_GRID - 1);
    __syncthreads();
    if (s_last) {                        // last block: out = colmean @ W2 + b2
        __shared__ float m[64];
        int t = threadIdx.x;
        if (t < 64) m[t] = g_csum[t * 32] * (1.0f / NN);
        __syncthreads();
        if (t < 64) {
            float s = b2[t];
            for (int k = 0; k < 64; k++) s += m[k] * W2[k * 64 + t];
            out[t] = s;
        }
    }
}

// ---------------- launch ----------------
extern "C" void kernel_launch(void* const* d_in, const int* in_sizes, int n_in,
                              void* d_out, int out_size) {
    const float* x   = (const float*)d_in[0];
    const void*  ei  = d_in[1];
    const float* W1  = (const float*)d_in[2];
    const float* as1 = (const float*)d_in[3];
    const float* ad1 = (const float*)d_in[4];
    const float* b1  = (const float*)d_in[5];
    const float* W2  = (const float*)d_in[6];
    const float* as2 = (const float*)d_in[7];
    const float* ad2 = (const float*)d_in[8];
    const float* b2  = (const float*)d_in[9];
    float* out = (float*)d_out;

    int gN = (NN + 255) / 256;           // 391
    int gQ = (NE / 4 + 255) / 256;       // 977 (quad-edge)
    int gW = NN / 16;                    // 6250 (warp-per-node, 512-thread blocks)

    k_init_prep<<<gN, 256>>>(x, (const int*)ei, W1, as1, ad1, W2, as2, ad2);
    k_scatter<<<gQ, 256>>>(ei);
    k_agg1<<<gW, 512>>>(W1, b1);
    k_agg2<<<AGG2_GRID, 256>>>(W2, b2, out);
}